// round 1
// baseline (speedup 1.0000x reference)
#include <cuda_runtime.h>
#include <math.h>

#define NTR 4096
#define NTE 8192
#define DD  8
#define NB  64

// ---------------- scratch (device globals: allocation-free) ----------------
__device__ float g_K[(size_t)NTR * NTR];   // K, becomes L (lower) in place
__device__ float g_V[(size_t)NTR * NTE];   // weighted K_s, becomes v in place
__device__ float g_alpha[NTR];             // rhs / solution of cho_solve
__device__ float g_par[3];                 // {0.5/ls^2, var, noise+1e-6}

// ---------------- params ----------------
__global__ void k_params(const float* rls, const float* rvar, const float* rnv) {
    if (threadIdx.x == 0) {
        float ls  = log1pf(expf(rls[0]));
        float var = log1pf(expf(rvar[0]));
        float nv  = log1pf(expf(rnv[0]));
        g_par[0] = 0.5f / (ls * ls);
        g_par[1] = var;
        g_par[2] = nv + 1e-6f;
    }
}

// ---------------- K = rbf(xtr,xtr) weighted + (noise)I ----------------
__global__ void k_buildK(const float* __restrict__ xtr, const float* __restrict__ w) {
    int j = blockIdx.x * 16 + threadIdx.x;
    int i = blockIdx.y * 16 + threadIdx.y;
    float p0 = g_par[0], var = g_par[1];
    float d2 = 0.f;
#pragma unroll
    for (int d = 0; d < DD; d++) {
        float df = xtr[i * DD + d] - xtr[j * DD + d];
        d2 += df * df;
    }
    float v;
    if (i == j) v = var + g_par[2];
    else        v = var * expf(-p0 * d2) * w[i] * w[j];
    g_K[(size_t)i * NTR + j] = v;
}

// ---------------- V = diag(w) * rbf(xtr, xte) ----------------
__global__ void k_buildKs(const float* __restrict__ xtr, const float* __restrict__ xte,
                          const float* __restrict__ w) {
    int t = blockIdx.x * 16 + threadIdx.x;
    int i = blockIdx.y * 16 + threadIdx.y;
    float p0 = g_par[0], var = g_par[1];
    float d2 = 0.f;
#pragma unroll
    for (int d = 0; d < DD; d++) {
        float df = xtr[i * DD + d] - xte[t * DD + d];
        d2 += df * df;
    }
    g_V[(size_t)i * NTE + t] = w[i] * var * expf(-p0 * d2);
}

// ---------------- Cholesky: 64x64 diagonal factor ----------------
__global__ void k_potrf(int k0) {
    __shared__ float s[NB][NB + 1];
    int tid = threadIdx.x;
    for (int idx = tid; idx < NB * NB; idx += blockDim.x)
        s[idx / NB][idx % NB] = g_K[(size_t)(k0 + idx / NB) * NTR + k0 + idx % NB];
    __syncthreads();
    for (int j = 0; j < NB; j++) {
        if (tid == 0) s[j][j] = sqrtf(s[j][j]);
        __syncthreads();
        float dinv = 1.f / s[j][j];
        for (int i = j + 1 + tid; i < NB; i += blockDim.x) s[i][j] *= dinv;
        __syncthreads();
        int rem = NB - 1 - j;
        for (int idx = tid; idx < rem * rem; idx += blockDim.x) {
            int ii = j + 1 + idx / rem;
            int cc = j + 1 + idx % rem;
            s[ii][cc] -= s[ii][j] * s[cc][j];   // upper garbage harmless (never read)
        }
        __syncthreads();
    }
    for (int idx = tid; idx < NB * NB; idx += blockDim.x)
        g_K[(size_t)(k0 + idx / NB) * NTR + k0 + idx % NB] = s[idx / NB][idx % NB];
}

// ---------------- Cholesky: panel trsm  X * Lkk^T = A ----------------
__global__ void k_panel(int k0) {
    __shared__ float Ls[NB][NB + 1];
    int tid = threadIdx.x;
    for (int idx = tid; idx < NB * NB; idx += blockDim.x)
        Ls[idx / NB][idx % NB] = g_K[(size_t)(k0 + idx / NB) * NTR + k0 + idx % NB];
    __syncthreads();
    int row = k0 + NB + blockIdx.x * blockDim.x + tid;
    if (row >= NTR) return;
    size_t base = (size_t)row * NTR + k0;
    float a[NB];
#pragma unroll
    for (int j = 0; j < NB; j++) a[j] = g_K[base + j];
#pragma unroll
    for (int j = 0; j < NB; j++) {
        float acc = a[j];
#pragma unroll
        for (int p = 0; p < j; p++) acc -= a[p] * Ls[j][p];
        a[j] = acc / Ls[j][j];
    }
#pragma unroll
    for (int j = 0; j < NB; j++) g_K[base + j] = a[j];
}

// ---------------- Cholesky: trailing SYRK  C -= P P^T (lower tiles) ----------------
__global__ void __launch_bounds__(256) k_syrk(int k0) {
    if (blockIdx.x > blockIdx.y) return;       // lower tiles only
    int t0 = k0 + NB;
    __shared__ float sA[64][NB + 1];
    __shared__ float sB[64][NB + 1];
    int tid = threadIdx.x;
    int tx = tid & 15, ty = tid >> 4;
    int rbase = t0 + blockIdx.y * 64;
    int cbase = t0 + blockIdx.x * 64;
    for (int idx = tid; idx < 64 * NB; idx += 256) {
        int r = idx / NB, p = idx % NB;
        sA[r][p] = g_K[(size_t)(rbase + r) * NTR + k0 + p];
        sB[r][p] = g_K[(size_t)(cbase + r) * NTR + k0 + p];
    }
    __syncthreads();
    float c[4][4];
#pragma unroll
    for (int i = 0; i < 4; i++)
#pragma unroll
        for (int j = 0; j < 4; j++) c[i][j] = 0.f;
#pragma unroll 8
    for (int p = 0; p < NB; p++) {
        float a[4], b[4];
#pragma unroll
        for (int i = 0; i < 4; i++) a[i] = sA[ty * 4 + i][p];
#pragma unroll
        for (int j = 0; j < 4; j++) b[j] = sB[tx * 4 + j][p];
#pragma unroll
        for (int i = 0; i < 4; i++)
#pragma unroll
            for (int j = 0; j < 4; j++) c[i][j] += a[i] * b[j];
    }
#pragma unroll
    for (int i = 0; i < 4; i++)
#pragma unroll
        for (int j = 0; j < 4; j++)
            g_K[(size_t)(rbase + ty * 4 + i) * NTR + cbase + tx * 4 + j] -= c[i][j];
}

// ---------------- alpha = cho_solve(L, y) ----------------
__global__ void k_copy_y(const float* __restrict__ y) {
    int i = blockIdx.x * blockDim.x + threadIdx.x;
    if (i < NTR) g_alpha[i] = y[i];
}

__global__ void k_fsolve(int k0) {   // forward, one 64 block
    __shared__ float Ls[NB][NB + 1];
    __shared__ float b[NB];
    int tid = threadIdx.x;
    for (int idx = tid; idx < NB * NB; idx += blockDim.x)
        Ls[idx / NB][idx % NB] = g_K[(size_t)(k0 + idx / NB) * NTR + k0 + idx % NB];
    b[tid] = g_alpha[k0 + tid];
    __syncthreads();
    for (int j = 0; j < NB; j++) {
        if (tid == 0) b[j] /= Ls[j][j];
        __syncthreads();
        if (tid > j) b[tid] -= Ls[tid][j] * b[j];
        __syncthreads();
    }
    g_alpha[k0 + tid] = b[tid];
}

__global__ void k_fupdate(int k0) {
    __shared__ float zc[NB];
    if (threadIdx.x < NB) zc[threadIdx.x] = g_alpha[k0 + threadIdx.x];
    __syncthreads();
    int r = k0 + NB + blockIdx.x * blockDim.x + threadIdx.x;
    if (r < NTR) {
        float acc = g_alpha[r];
#pragma unroll
        for (int j = 0; j < NB; j++) acc -= g_K[(size_t)r * NTR + k0 + j] * zc[j];
        g_alpha[r] = acc;
    }
}

__global__ void k_bsolve(int k0) {   // backward with L^T
    __shared__ float Ls[NB][NB + 1];
    __shared__ float b[NB];
    int tid = threadIdx.x;
    for (int idx = tid; idx < NB * NB; idx += blockDim.x)
        Ls[idx / NB][idx % NB] = g_K[(size_t)(k0 + idx / NB) * NTR + k0 + idx % NB];
    b[tid] = g_alpha[k0 + tid];
    __syncthreads();
    for (int j = NB - 1; j >= 0; j--) {
        if (tid == 0) b[j] /= Ls[j][j];
        __syncthreads();
        if (tid < j) b[tid] -= Ls[j][tid] * b[j];
        __syncthreads();
    }
    g_alpha[k0 + tid] = b[tid];
}

__global__ void k_bupdate(int k0) {
    __shared__ float zc[NB];
    if (threadIdx.x < NB) zc[threadIdx.x] = g_alpha[k0 + threadIdx.x];
    __syncthreads();
    int r = blockIdx.x * blockDim.x + threadIdx.x;
    if (r < k0) {
        float acc = g_alpha[r];
#pragma unroll
        for (int j = 0; j < NB; j++) acc -= g_K[(size_t)(k0 + j) * NTR + r] * zc[j];
        g_alpha[r] = acc;
    }
}

// ---------------- mu = V^T alpha (before V is overwritten) ----------------
__global__ void k_mu(float* __restrict__ out) {
    int t = blockIdx.x * blockDim.x + threadIdx.x;
    float acc = 0.f;
#pragma unroll 8
    for (int i = 0; i < NTR; i++) acc += g_V[(size_t)i * NTE + t] * g_alpha[i];
    out[t] = acc;
}

// ---------------- big trsm: V <- L^{-1} V (left-looking blocked) ----------------
// GEMM update: V[k0..k0+64, :] -= L[k0..k0+64, 0..k0) @ V[0..k0, :]
__global__ void __launch_bounds__(256) k_gemmV(int k0) {
    __shared__ float sA[16][NB + 4];   // [p][r]
    __shared__ float sB[16][132];      // [p][c]
    int tid = threadIdx.x;
    int tx = tid & 15, ty = tid >> 4;
    int cbase = blockIdx.x * 128;
    float c[4][8];
#pragma unroll
    for (int i = 0; i < 4; i++)
#pragma unroll
        for (int j = 0; j < 8; j++) c[i][j] = 0.f;
    for (int kk = 0; kk < k0; kk += 16) {
#pragma unroll
        for (int l = 0; l < 4; l++) {
            int idx = tid + l * 256;
            int r = idx >> 4, p = idx & 15;
            sA[p][r] = g_K[(size_t)(k0 + r) * NTR + kk + p];
        }
#pragma unroll
        for (int l = 0; l < 8; l++) {
            int idx = tid + l * 256;
            int p = idx >> 7, cc = idx & 127;
            sB[p][cc] = g_V[(size_t)(kk + p) * NTE + cbase + cc];
        }
        __syncthreads();
#pragma unroll
        for (int p = 0; p < 16; p++) {
            float a[4], b[8];
#pragma unroll
            for (int i = 0; i < 4; i++) a[i] = sA[p][ty * 4 + i];
            *(float4*)&b[0] = *(const float4*)&sB[p][tx * 8];
            *(float4*)&b[4] = *(const float4*)&sB[p][tx * 8 + 4];
#pragma unroll
            for (int i = 0; i < 4; i++)
#pragma unroll
                for (int j = 0; j < 8; j++) c[i][j] += a[i] * b[j];
        }
        __syncthreads();
    }
#pragma unroll
    for (int i = 0; i < 4; i++)
#pragma unroll
        for (int j = 0; j < 8; j++)
            g_V[(size_t)(k0 + ty * 4 + i) * NTE + cbase + tx * 8 + j] -= c[i][j];
}

// diag solve: V[k0..k0+64, :] <- Lkk^{-1} V[k0..k0+64, :]
__global__ void k_diagV(int k0) {
    __shared__ float Ls[NB][NB + 1];
    int tid = threadIdx.x;
    for (int idx = tid; idx < NB * NB; idx += blockDim.x)
        Ls[idx / NB][idx % NB] = g_K[(size_t)(k0 + idx / NB) * NTR + k0 + idx % NB];
    __syncthreads();
    int t = blockIdx.x * blockDim.x + tid;
    float x[NB];
#pragma unroll
    for (int r = 0; r < NB; r++) {
        float acc = g_V[(size_t)(k0 + r) * NTE + t];
#pragma unroll
        for (int p = 0; p < r; p++) acc -= Ls[r][p] * x[p];
        x[r] = acc / Ls[r][r];
        g_V[(size_t)(k0 + r) * NTE + t] = x[r];
    }
}

// ---------------- cov = K_ss - v^T v (symmetric, fused epilogue) ----------------
__global__ void __launch_bounds__(256) k_cov(const float* __restrict__ xte,
                                             float* __restrict__ C) {
    int ta = blockIdx.y, tb = blockIdx.x;
    if (tb < ta) return;                          // upper tiles only, mirror on write
    __shared__ float sA[16][132];
    __shared__ float sB[16][132];
    __shared__ float sXa[128][8];
    __shared__ float sXb[128][8];
    int tid = threadIdx.x;
    int tx = tid & 15, ty = tid >> 4;
    for (int idx = tid; idx < 128 * 8; idx += 256) {
        sXa[idx >> 3][idx & 7] = xte[(size_t)(ta * 128 + (idx >> 3)) * 8 + (idx & 7)];
        sXb[idx >> 3][idx & 7] = xte[(size_t)(tb * 128 + (idx >> 3)) * 8 + (idx & 7)];
    }
    float c[8][8];
#pragma unroll
    for (int i = 0; i < 8; i++)
#pragma unroll
        for (int j = 0; j < 8; j++) c[i][j] = 0.f;

    for (int kk = 0; kk < NTR; kk += 16) {
#pragma unroll
        for (int l = 0; l < 8; l++) {
            int idx = tid + l * 256;
            int p = idx >> 7, cc = idx & 127;
            sA[p][cc] = g_V[(size_t)(kk + p) * NTE + ta * 128 + cc];
            sB[p][cc] = g_V[(size_t)(kk + p) * NTE + tb * 128 + cc];
        }
        __syncthreads();
#pragma unroll
        for (int p = 0; p < 16; p++) {
            float a[8], b[8];
            *(float4*)&a[0] = *(const float4*)&sA[p][ty * 8];
            *(float4*)&a[4] = *(const float4*)&sA[p][ty * 8 + 4];
            *(float4*)&b[0] = *(const float4*)&sB[p][tx * 8];
            *(float4*)&b[4] = *(const float4*)&sB[p][tx * 8 + 4];
#pragma unroll
            for (int i = 0; i < 8; i++)
#pragma unroll
                for (int j = 0; j < 8; j++) c[i][j] += a[i] * b[j];
        }
        __syncthreads();
    }
    float p0 = g_par[0], var = g_par[1];
#pragma unroll
    for (int i = 0; i < 8; i++) {
        int ga = ta * 128 + ty * 8 + i;
#pragma unroll
        for (int j = 0; j < 8; j++) {
            int gb = tb * 128 + tx * 8 + j;
            float d2 = 0.f;
#pragma unroll
            for (int d = 0; d < 8; d++) {
                float df = sXa[ty * 8 + i][d] - sXb[tx * 8 + j][d];
                d2 += df * df;
            }
            float val = var * expf(-p0 * d2) - c[i][j];
            if (ga == gb) val += 1e-6f;
            C[(size_t)ga * NTE + gb] = val;
            C[(size_t)gb * NTE + ga] = val;
        }
    }
}

// ---------------- driver ----------------
extern "C" void kernel_launch(void* const* d_in, const int* in_sizes, int n_in,
                              void* d_out, int out_size) {
    (void)in_sizes; (void)n_in; (void)out_size;
    const float* x_train = (const float*)d_in[0];
    const float* y_train = (const float*)d_in[1];
    const float* w_train = (const float*)d_in[2];
    const float* x_test  = (const float*)d_in[3];
    const float* rls     = (const float*)d_in[4];
    const float* rvar    = (const float*)d_in[5];
    const float* rnv     = (const float*)d_in[6];
    float* out = (float*)d_out;          // [ mu (8192) | cov (8192*8192) ]

    k_params<<<1, 32>>>(rls, rvar, rnv);

    dim3 b16(16, 16);
    k_buildK <<<dim3(NTR / 16, NTR / 16), b16>>>(x_train, w_train);
    k_buildKs<<<dim3(NTE / 16, NTR / 16), b16>>>(x_train, x_test, w_train);

    // blocked Cholesky (in place in g_K)
    for (int k0 = 0; k0 < NTR; k0 += NB) {
        k_potrf<<<1, 256>>>(k0);
        int rows = NTR - k0 - NB;
        if (rows > 0) {
            k_panel<<<(rows + 63) / 64, 64>>>(k0);
            int nt = rows / 64;
            k_syrk<<<dim3(nt, nt), 256>>>(k0);
        }
    }

    // alpha = cho_solve(L, y)
    k_copy_y<<<(NTR + 255) / 256, 256>>>(y_train);
    for (int k0 = 0; k0 < NTR; k0 += NB) {
        k_fsolve<<<1, NB>>>(k0);
        int rows = NTR - k0 - NB;
        if (rows > 0) k_fupdate<<<(rows + 255) / 256, 256>>>(k0);
    }
    for (int k0 = NTR - NB; k0 >= 0; k0 -= NB) {
        k_bsolve<<<1, NB>>>(k0);
        if (k0 > 0) k_bupdate<<<(k0 + 255) / 256, 256>>>(k0);
    }

    // mu (uses weighted K_s before trsm overwrites it)
    k_mu<<<NTE / 128, 128>>>(out);

    // v = L^{-1} V (in place)
    for (int k0 = 0; k0 < NTR; k0 += NB) {
        if (k0 > 0) k_gemmV<<<dim3(NTE / 128, 1), 256>>>(k0);
        k_diagV<<<NTE / 128, 128>>>(k0);
    }

    // cov = K_ss - v^T v
    k_cov<<<dim3(NTE / 128, NTE / 128), 256>>>(x_test, out + NTE);
}

// round 2
// speedup vs baseline: 1.5708x; 1.5708x over previous
#include <cuda_runtime.h>
#include <math.h>

#define NTR 4096
#define NTE 8192
#define DD  8
#define NB  64
#define LDV 8320   // NTE + 128 pad; col 8192 carries z = L^{-1} y

// ---------------- scratch (device globals: allocation-free) ----------------
__device__ float g_K[(size_t)NTR * NTR];   // K, becomes L (lower) in place
__device__ float g_V[(size_t)NTR * LDV];   // [w*K_s | z | zero-pad], becomes L^{-1}(...) in place
__device__ float g_par[3];                 // {0.5/ls^2, var, noise+1e-6}

// ---------------- params ----------------
__global__ void k_params(const float* rls, const float* rvar, const float* rnv) {
    if (threadIdx.x == 0) {
        float ls  = log1pf(expf(rls[0]));
        float var = log1pf(expf(rvar[0]));
        float nv  = log1pf(expf(rnv[0]));
        g_par[0] = 0.5f / (ls * ls);
        g_par[1] = var;
        g_par[2] = nv + 1e-6f;
    }
}

// ---------------- K = rbf(xtr,xtr) weighted + (noise)I ----------------
__global__ void k_buildK(const float* __restrict__ xtr, const float* __restrict__ w) {
    int j = blockIdx.x * 16 + threadIdx.x;
    int i = blockIdx.y * 16 + threadIdx.y;
    float p0 = g_par[0], var = g_par[1];
    float d2 = 0.f;
#pragma unroll
    for (int d = 0; d < DD; d++) {
        float df = xtr[i * DD + d] - xtr[j * DD + d];
        d2 += df * df;
    }
    float v;
    if (i == j) v = var + g_par[2];
    else        v = var * expf(-p0 * d2) * w[i] * w[j];
    g_K[(size_t)i * NTR + j] = v;
}

// ---------------- V[:,0:8192] = diag(w) * rbf(xtr, xte) ----------------
__global__ void k_buildKs(const float* __restrict__ xtr, const float* __restrict__ xte,
                          const float* __restrict__ w) {
    int t = blockIdx.x * 16 + threadIdx.x;
    int i = blockIdx.y * 16 + threadIdx.y;
    float p0 = g_par[0], var = g_par[1];
    float d2 = 0.f;
#pragma unroll
    for (int d = 0; d < DD; d++) {
        float df = xtr[i * DD + d] - xte[t * DD + d];
        d2 += df * df;
    }
    g_V[(size_t)i * LDV + t] = w[i] * var * expf(-p0 * d2);
}

// ---------------- V[:,8192] = y ; V[:,8193..] = 0 ----------------
__global__ void k_initz(const float* __restrict__ y) {
    int i = blockIdx.x;
    int c = threadIdx.x;           // 0..127
    g_V[(size_t)i * LDV + NTE + c] = (c == 0) ? y[i] : 0.f;
}

// ---------------- Cholesky: 64x64 diagonal factor, register rows ----------------
__global__ void __launch_bounds__(64) k_potrf(int k0) {
    __shared__ float colbuf[NB];
    __shared__ float sdinv;
    int tid = threadIdx.x;
    float a[NB];
    size_t base = (size_t)(k0 + tid) * NTR + k0;
#pragma unroll
    for (int p = 0; p < NB; p++) a[p] = g_K[base + p];
#pragma unroll
    for (int j = 0; j < NB; j++) {
        if (tid == j) {
            float d = sqrtf(a[j]);
            a[j] = d;
            colbuf[j] = d;
            sdinv = 1.f / d;
        }
        __syncthreads();
        float lij = a[j] * sdinv;
        if (tid > j) { colbuf[tid] = lij; a[j] = lij; }
        __syncthreads();
        if (tid > j) {
#pragma unroll
            for (int p = j + 1; p < NB; p++)
                if (p <= tid) a[p] -= lij * colbuf[p];
        }
        __syncthreads();
    }
#pragma unroll
    for (int p = 0; p < NB; p++)
        if (p <= tid) g_K[base + p] = a[p];
}

// ---------------- Cholesky: panel trsm  X * Lkk^T = A ----------------
__global__ void k_panel(int k0) {
    __shared__ float Ls[NB][NB + 1];
    int tid = threadIdx.x;
    for (int idx = tid; idx < NB * NB; idx += blockDim.x)
        Ls[idx / NB][idx % NB] = g_K[(size_t)(k0 + idx / NB) * NTR + k0 + idx % NB];
    __syncthreads();
    int row = k0 + NB + blockIdx.x * blockDim.x + tid;
    if (row >= NTR) return;
    size_t base = (size_t)row * NTR + k0;
    float a[NB];
#pragma unroll
    for (int j = 0; j < NB; j++) a[j] = g_K[base + j];
#pragma unroll
    for (int j = 0; j < NB; j++) {
        float acc = a[j];
#pragma unroll
        for (int p = 0; p < j; p++) acc -= a[p] * Ls[j][p];
        a[j] = acc / Ls[j][j];
    }
#pragma unroll
    for (int j = 0; j < NB; j++) g_K[base + j] = a[j];
}

// ---------------- Cholesky: trailing SYRK  C -= P P^T (lower tiles) ----------------
__global__ void __launch_bounds__(256) k_syrk(int k0) {
    if (blockIdx.x > blockIdx.y) return;
    int t0 = k0 + NB;
    __shared__ float sA[64][NB + 1];
    __shared__ float sB[64][NB + 1];
    int tid = threadIdx.x;
    int tx = tid & 15, ty = tid >> 4;
    int rbase = t0 + blockIdx.y * 64;
    int cbase = t0 + blockIdx.x * 64;
    for (int idx = tid; idx < 64 * NB; idx += 256) {
        int r = idx / NB, p = idx % NB;
        sA[r][p] = g_K[(size_t)(rbase + r) * NTR + k0 + p];
        sB[r][p] = g_K[(size_t)(cbase + r) * NTR + k0 + p];
    }
    __syncthreads();
    float c[4][4];
#pragma unroll
    for (int i = 0; i < 4; i++)
#pragma unroll
        for (int j = 0; j < 4; j++) c[i][j] = 0.f;
#pragma unroll 8
    for (int p = 0; p < NB; p++) {
        float a[4], b[4];
#pragma unroll
        for (int i = 0; i < 4; i++) a[i] = sA[ty * 4 + i][p];
#pragma unroll
        for (int j = 0; j < 4; j++) b[j] = sB[tx * 4 + j][p];
#pragma unroll
        for (int i = 0; i < 4; i++)
#pragma unroll
            for (int j = 0; j < 4; j++) c[i][j] += a[i] * b[j];
    }
#pragma unroll
    for (int i = 0; i < 4; i++)
#pragma unroll
        for (int j = 0; j < 4; j++)
            g_K[(size_t)(rbase + ty * 4 + i) * NTR + cbase + tx * 4 + j] -= c[i][j];
}

// ---------------- trsm diag: V[k0..k0+64, :] <- Lkk^{-1} V[k0..k0+64, :] ----------------
__global__ void k_diagV(int k0) {
    __shared__ float Ls[NB][NB + 1];
    int tid = threadIdx.x;
    for (int idx = tid; idx < NB * NB; idx += blockDim.x)
        Ls[idx / NB][idx % NB] = g_K[(size_t)(k0 + idx / NB) * NTR + k0 + idx % NB];
    __syncthreads();
    int t = blockIdx.x * blockDim.x + tid;
    float x[NB];
#pragma unroll
    for (int r = 0; r < NB; r++) {
        float acc = g_V[(size_t)(k0 + r) * LDV + t];
#pragma unroll
        for (int p = 0; p < r; p++) acc -= Ls[r][p] * x[p];
        x[r] = acc / Ls[r][r];
        g_V[(size_t)(k0 + r) * LDV + t] = x[r];
    }
}

// ---------------- trsm right-looking update:
// V[k0+64.., :] -= L[k0+64.., k0 blk] @ V[k0 blk, :]   (tile 64r x 128c, K=64)
__global__ void __launch_bounds__(256) k_trsm_update(int k0) {
    __shared__ float sL[16][68];    // [p][r]
    __shared__ float sV[16][132];   // [p][c]
    int tid = threadIdx.x;
    int tx = tid & 15, ty = tid >> 4;
    int r0 = k0 + NB + blockIdx.y * 64;
    int c0 = blockIdx.x * 128;
    float c[4][8];
#pragma unroll
    for (int i = 0; i < 4; i++)
#pragma unroll
        for (int j = 0; j < 8; j++) c[i][j] = 0.f;

    for (int kk = 0; kk < NB; kk += 16) {
        {   // L tile: 64 rows x 16 k, transposed into sL
            int r = tid >> 2, pv = (tid & 3) * 4;
            float4 t4 = *(const float4*)&g_K[(size_t)(r0 + r) * NTR + k0 + kk + pv];
            sL[pv + 0][r] = t4.x; sL[pv + 1][r] = t4.y;
            sL[pv + 2][r] = t4.z; sL[pv + 3][r] = t4.w;
        }
        {   // V tile: 16 k x 128 c (512 float4)
#pragma unroll
            for (int l = 0; l < 2; l++) {
                int idx = tid + l * 256;
                int p = idx >> 5, cc = (idx & 31) * 4;
                *(float4*)&sV[p][cc] =
                    *(const float4*)&g_V[(size_t)(k0 + kk + p) * LDV + c0 + cc];
            }
        }
        __syncthreads();
#pragma unroll
        for (int p = 0; p < 16; p++) {
            float a[4], b[8];
#pragma unroll
            for (int i = 0; i < 4; i++) a[i] = sL[p][ty * 4 + i];
            *(float4*)&b[0] = *(const float4*)&sV[p][tx * 8];
            *(float4*)&b[4] = *(const float4*)&sV[p][tx * 8 + 4];
#pragma unroll
            for (int i = 0; i < 4; i++)
#pragma unroll
                for (int j = 0; j < 8; j++) c[i][j] += a[i] * b[j];
        }
        __syncthreads();
    }
#pragma unroll
    for (int i = 0; i < 4; i++)
#pragma unroll
        for (int j = 0; j < 8; j++)
            g_V[(size_t)(r0 + ty * 4 + i) * LDV + c0 + tx * 8 + j] -= c[i][j];
}

// ---------------- mu = v^T z  (z = V[:,8192]) ----------------
__global__ void k_mu(float* __restrict__ out) {
    int t = blockIdx.x * blockDim.x + threadIdx.x;
    float acc = 0.f;
#pragma unroll 8
    for (int i = 0; i < NTR; i++)
        acc += g_V[(size_t)i * LDV + t] * g_V[(size_t)i * LDV + NTE];
    out[t] = acc;
}

// ---------------- cov = K_ss - v^T v (symmetric, fused epilogue) ----------------
__global__ void __launch_bounds__(256) k_cov(const float* __restrict__ xte,
                                             float* __restrict__ C) {
    int ta = blockIdx.y, tb = blockIdx.x;
    if (tb < ta) return;                          // upper tiles only, mirror on write
    __shared__ float sA[16][132];
    __shared__ float sB[16][132];
    __shared__ float sXa[128][8];
    __shared__ float sXb[128][8];
    int tid = threadIdx.x;
    int tx = tid & 15, ty = tid >> 4;
    for (int idx = tid; idx < 128 * 8; idx += 256) {
        sXa[idx >> 3][idx & 7] = xte[(size_t)(ta * 128 + (idx >> 3)) * 8 + (idx & 7)];
        sXb[idx >> 3][idx & 7] = xte[(size_t)(tb * 128 + (idx >> 3)) * 8 + (idx & 7)];
    }
    float c[8][8];
#pragma unroll
    for (int i = 0; i < 8; i++)
#pragma unroll
        for (int j = 0; j < 8; j++) c[i][j] = 0.f;

    for (int kk = 0; kk < NTR; kk += 16) {
#pragma unroll
        for (int l = 0; l < 2; l++) {
            int idx = tid + l * 256;
            int p = idx >> 5, cc = (idx & 31) * 4;
            *(float4*)&sA[p][cc] = *(const float4*)&g_V[(size_t)(kk + p) * LDV + ta * 128 + cc];
            *(float4*)&sB[p][cc] = *(const float4*)&g_V[(size_t)(kk + p) * LDV + tb * 128 + cc];
        }
        __syncthreads();
#pragma unroll
        for (int p = 0; p < 16; p++) {
            float a[8], b[8];
            *(float4*)&a[0] = *(const float4*)&sA[p][ty * 8];
            *(float4*)&a[4] = *(const float4*)&sA[p][ty * 8 + 4];
            *(float4*)&b[0] = *(const float4*)&sB[p][tx * 8];
            *(float4*)&b[4] = *(const float4*)&sB[p][tx * 8 + 4];
#pragma unroll
            for (int i = 0; i < 8; i++)
#pragma unroll
                for (int j = 0; j < 8; j++) c[i][j] += a[i] * b[j];
        }
        __syncthreads();
    }
    float p0 = g_par[0], var = g_par[1];
#pragma unroll
    for (int i = 0; i < 8; i++) {
        int ga = ta * 128 + ty * 8 + i;
#pragma unroll
        for (int j = 0; j < 8; j++) {
            int gb = tb * 128 + tx * 8 + j;
            float d2 = 0.f;
#pragma unroll
            for (int d = 0; d < 8; d++) {
                float df = sXa[ty * 8 + i][d] - sXb[tx * 8 + j][d];
                d2 += df * df;
            }
            float val = var * expf(-p0 * d2) - c[i][j];
            if (ga == gb) val += 1e-6f;
            C[(size_t)ga * NTE + gb] = val;
            C[(size_t)gb * NTE + ga] = val;
        }
    }
}

// ---------------- driver ----------------
extern "C" void kernel_launch(void* const* d_in, const int* in_sizes, int n_in,
                              void* d_out, int out_size) {
    (void)in_sizes; (void)n_in; (void)out_size;
    const float* x_train = (const float*)d_in[0];
    const float* y_train = (const float*)d_in[1];
    const float* w_train = (const float*)d_in[2];
    const float* x_test  = (const float*)d_in[3];
    const float* rls     = (const float*)d_in[4];
    const float* rvar    = (const float*)d_in[5];
    const float* rnv     = (const float*)d_in[6];
    float* out = (float*)d_out;          // [ mu (8192) | cov (8192*8192) ]

    k_params<<<1, 32>>>(rls, rvar, rnv);

    dim3 b16(16, 16);
    k_buildK <<<dim3(NTR / 16, NTR / 16), b16>>>(x_train, w_train);
    k_buildKs<<<dim3(NTE / 16, NTR / 16), b16>>>(x_train, x_test, w_train);
    k_initz  <<<NTR, 128>>>(y_train);

    // blocked Cholesky (in place in g_K)
    for (int k0 = 0; k0 < NTR; k0 += NB) {
        k_potrf<<<1, 64>>>(k0);
        int rows = NTR - k0 - NB;
        if (rows > 0) {
            k_panel<<<(rows + 63) / 64, 64>>>(k0);
            int nt = rows / 64;
            k_syrk<<<dim3(nt, nt), 256>>>(k0);
        }
    }

    // v = L^{-1} [wKs | y | 0]  (right-looking blocked forward substitution)
    for (int k0 = 0; k0 < NTR; k0 += NB) {
        k_diagV<<<LDV / 128, 128>>>(k0);
        int rows = NTR - k0 - NB;
        if (rows > 0)
            k_trsm_update<<<dim3(LDV / 128, rows / 64), 256>>>(k0);
    }

    // mu = v^T z
    k_mu<<<NTE / 128, 128>>>(out);

    // cov = K_ss - v^T v
    k_cov<<<dim3(NTE / 128, NTE / 128), 256>>>(x_test, out + NTE);
}

// round 3
// speedup vs baseline: 1.5927x; 1.0139x over previous
#include <cuda_runtime.h>
#include <math.h>

#define NTR 4096
#define NTE 8192
#define DD  8
#define NB  64
#define LDV 8320   // NTE + 128 pad; col 8192 carries z = L^{-1} y

typedef unsigned long long ull;

// ---------------- f32x2 packed-FMA helpers (SASS FFMA2; PTX-only path) ------
__device__ __forceinline__ ull pack2(float lo, float hi) {
    ull r; asm("mov.b64 %0, {%1,%2};" : "=l"(r) : "f"(lo), "f"(hi)); return r;
}
__device__ __forceinline__ void fma2(ull& d, ull a, ull b) {
    asm("fma.rn.f32x2 %0, %1, %2, %0;" : "+l"(d) : "l"(a), "l"(b));
}
__device__ __forceinline__ void unpack2(ull v, float& lo, float& hi) {
    asm("mov.b64 {%0,%1}, %2;" : "=f"(lo), "=f"(hi) : "l"(v));
}

// ---------------- scratch (device globals: allocation-free) ----------------
__device__ float g_K[(size_t)NTR * NTR];   // K, becomes L (lower) in place
__device__ float g_V[(size_t)NTR * LDV];   // [w*K_s | z | pad], becomes L^{-1}(...)
__device__ float g_par[3];                 // {0.5/ls^2, var, noise+1e-6}

// ---------------- params ----------------
__global__ void k_params(const float* rls, const float* rvar, const float* rnv) {
    if (threadIdx.x == 0) {
        float ls  = log1pf(expf(rls[0]));
        float var = log1pf(expf(rvar[0]));
        float nv  = log1pf(expf(rnv[0]));
        g_par[0] = 0.5f / (ls * ls);
        g_par[1] = var;
        g_par[2] = nv + 1e-6f;
    }
}

// ---------------- K = rbf(xtr,xtr) weighted + (noise)I ----------------
__global__ void k_buildK(const float* __restrict__ xtr, const float* __restrict__ w) {
    int j = blockIdx.x * 16 + threadIdx.x;
    int i = blockIdx.y * 16 + threadIdx.y;
    float p0 = g_par[0], var = g_par[1];
    float d2 = 0.f;
#pragma unroll
    for (int d = 0; d < DD; d++) {
        float df = xtr[i * DD + d] - xtr[j * DD + d];
        d2 += df * df;
    }
    float v;
    if (i == j) v = var + g_par[2];
    else        v = var * expf(-p0 * d2) * w[i] * w[j];
    g_K[(size_t)i * NTR + j] = v;
}

// ---------------- V[:,0:8192] = diag(w) * rbf(xtr, xte) ----------------
__global__ void k_buildKs(const float* __restrict__ xtr, const float* __restrict__ xte,
                          const float* __restrict__ w) {
    int t = blockIdx.x * 16 + threadIdx.x;
    int i = blockIdx.y * 16 + threadIdx.y;
    float p0 = g_par[0], var = g_par[1];
    float d2 = 0.f;
#pragma unroll
    for (int d = 0; d < DD; d++) {
        float df = xtr[i * DD + d] - xte[t * DD + d];
        d2 += df * df;
    }
    g_V[(size_t)i * LDV + t] = w[i] * var * expf(-p0 * d2);
}

// ---------------- V[:,8192] = y ; V[:,8193..] = 0 ----------------
__global__ void k_initz(const float* __restrict__ y) {
    int i = blockIdx.x;
    int c = threadIdx.x;
    g_V[(size_t)i * LDV + NTE + c] = (c == 0) ? y[i] : 0.f;
}

// ---------------- Cholesky: 64x64 diagonal factor, register rows ----------------
__global__ void __launch_bounds__(64) k_potrf(int k0) {
    __shared__ float colbuf[NB];
    __shared__ float sdinv;
    int tid = threadIdx.x;
    float a[NB];
    size_t base = (size_t)(k0 + tid) * NTR + k0;
#pragma unroll
    for (int p = 0; p < NB; p++) a[p] = g_K[base + p];
#pragma unroll
    for (int j = 0; j < NB; j++) {
        if (tid == j) {
            float d = sqrtf(a[j]);
            a[j] = d;
            colbuf[j] = d;
            sdinv = 1.f / d;
        }
        __syncthreads();
        float lij = a[j] * sdinv;
        if (tid > j) { colbuf[tid] = lij; a[j] = lij; }
        __syncthreads();
        if (tid > j) {
#pragma unroll
            for (int p = j + 1; p < NB; p++)
                if (p <= tid) a[p] -= lij * colbuf[p];
        }
        __syncthreads();
    }
#pragma unroll
    for (int p = 0; p < NB; p++)
        if (p <= tid) g_K[base + p] = a[p];
}

// ---------------- Cholesky: panel trsm  X * Lkk^T = A ----------------
__global__ void k_panel(int k0) {
    __shared__ float Ls[NB][NB + 1];
    int tid = threadIdx.x;
    for (int idx = tid; idx < NB * NB; idx += blockDim.x)
        Ls[idx / NB][idx % NB] = g_K[(size_t)(k0 + idx / NB) * NTR + k0 + idx % NB];
    __syncthreads();
    int row = k0 + NB + blockIdx.x * blockDim.x + tid;
    if (row >= NTR) return;
    size_t base = (size_t)row * NTR + k0;
    float a[NB];
#pragma unroll
    for (int j = 0; j < NB; j++) a[j] = g_K[base + j];
#pragma unroll
    for (int j = 0; j < NB; j++) {
        float acc = a[j];
#pragma unroll
        for (int p = 0; p < j; p++) acc -= a[p] * Ls[j][p];
        a[j] = acc / Ls[j][j];
    }
#pragma unroll
    for (int j = 0; j < NB; j++) g_K[base + j] = a[j];
}

// ---------------- Cholesky: trailing SYRK  C -= P P^T (lower tiles, f32x2) ----
__global__ void __launch_bounds__(256) k_syrk(int k0) {
    if (blockIdx.x > blockIdx.y) return;
    __shared__ float sA[NB][68];   // [p][r] (transposed at load)
    __shared__ float sB[NB][68];
    int tid = threadIdx.x;
    int tx = tid & 15, ty = tid >> 4;
    int rbase = k0 + NB + blockIdx.y * 64;
    int cbase = k0 + NB + blockIdx.x * 64;
    {
        int r = tid >> 2, pv = (tid & 3) * 16;
#pragma unroll
        for (int q = 0; q < 4; q++) {
            float4 tA = *(const float4*)&g_K[(size_t)(rbase + r) * NTR + k0 + pv + q * 4];
            sA[pv + q * 4 + 0][r] = tA.x; sA[pv + q * 4 + 1][r] = tA.y;
            sA[pv + q * 4 + 2][r] = tA.z; sA[pv + q * 4 + 3][r] = tA.w;
            float4 tB = *(const float4*)&g_K[(size_t)(cbase + r) * NTR + k0 + pv + q * 4];
            sB[pv + q * 4 + 0][r] = tB.x; sB[pv + q * 4 + 1][r] = tB.y;
            sB[pv + q * 4 + 2][r] = tB.z; sB[pv + q * 4 + 3][r] = tB.w;
        }
    }
    __syncthreads();
    ull c2[4][2];
#pragma unroll
    for (int i = 0; i < 4; i++) { c2[i][0] = 0ull; c2[i][1] = 0ull; }
#pragma unroll 8
    for (int p = 0; p < NB; p++) {
        ull b2[2];
        b2[0] = *(const ull*)&sB[p][tx * 4];
        b2[1] = *(const ull*)&sB[p][tx * 4 + 2];
#pragma unroll
        for (int i = 0; i < 4; i++) {
            float av = sA[p][ty * 4 + i];
            ull a2 = pack2(av, av);
            fma2(c2[i][0], a2, b2[0]);
            fma2(c2[i][1], a2, b2[1]);
        }
    }
#pragma unroll
    for (int i = 0; i < 4; i++) {
        float c0, c1, c2v, c3;
        unpack2(c2[i][0], c0, c1);
        unpack2(c2[i][1], c2v, c3);
        size_t rowb = (size_t)(rbase + ty * 4 + i) * NTR + cbase + tx * 4;
        g_K[rowb + 0] -= c0; g_K[rowb + 1] -= c1;
        g_K[rowb + 2] -= c2v; g_K[rowb + 3] -= c3;
    }
}

// ---------------- trsm diag: V[k0..k0+64, :] <- Lkk^{-1} V[k0..k0+64, :] ------
__global__ void k_diagV(int k0) {
    __shared__ float Ls[NB][NB + 1];
    int tid = threadIdx.x;
    for (int idx = tid; idx < NB * NB; idx += blockDim.x)
        Ls[idx / NB][idx % NB] = g_K[(size_t)(k0 + idx / NB) * NTR + k0 + idx % NB];
    __syncthreads();
    int t = blockIdx.x * blockDim.x + tid;
    float x[NB];
#pragma unroll
    for (int r = 0; r < NB; r++) {
        float acc = g_V[(size_t)(k0 + r) * LDV + t];
#pragma unroll
        for (int p = 0; p < r; p++) acc -= Ls[r][p] * x[p];
        x[r] = acc / Ls[r][r];
        g_V[(size_t)(k0 + r) * LDV + t] = x[r];
    }
}

// ---------------- trsm right-looking update (f32x2):
// V[k0+64.., :] -= L[k0+64.., k0 blk] @ V[k0 blk, :]   (tile 64r x 128c, K=64)
__global__ void __launch_bounds__(256) k_trsm_update(int k0) {
    __shared__ float sL[16][68];    // [p][r]
    __shared__ float sV[16][132];   // [p][c]
    int tid = threadIdx.x;
    int tx = tid & 15, ty = tid >> 4;
    int r0 = k0 + NB + blockIdx.y * 64;
    int c0 = blockIdx.x * 128;
    ull c2[4][4];
#pragma unroll
    for (int i = 0; i < 4; i++)
#pragma unroll
        for (int j = 0; j < 4; j++) c2[i][j] = 0ull;

    for (int kk = 0; kk < NB; kk += 16) {
        {
            int r = tid >> 2, pv = (tid & 3) * 4;
            float4 t4 = *(const float4*)&g_K[(size_t)(r0 + r) * NTR + k0 + kk + pv];
            sL[pv + 0][r] = t4.x; sL[pv + 1][r] = t4.y;
            sL[pv + 2][r] = t4.z; sL[pv + 3][r] = t4.w;
        }
#pragma unroll
        for (int l = 0; l < 2; l++) {
            int idx = tid + l * 256;
            int p = idx >> 5, cc = (idx & 31) * 4;
            *(float4*)&sV[p][cc] =
                *(const float4*)&g_V[(size_t)(k0 + kk + p) * LDV + c0 + cc];
        }
        __syncthreads();
#pragma unroll
        for (int p = 0; p < 16; p++) {
            ull b2[4];
#pragma unroll
            for (int j = 0; j < 4; j++)
                b2[j] = *(const ull*)&sV[p][tx * 8 + 2 * j];
#pragma unroll
            for (int i = 0; i < 4; i++) {
                float av = sL[p][ty * 4 + i];
                ull a2 = pack2(av, av);
#pragma unroll
                for (int j = 0; j < 4; j++) fma2(c2[i][j], a2, b2[j]);
            }
        }
        __syncthreads();
    }
#pragma unroll
    for (int i = 0; i < 4; i++) {
        size_t rowb = (size_t)(r0 + ty * 4 + i) * LDV + c0 + tx * 8;
#pragma unroll
        for (int j = 0; j < 4; j++) {
            float lo, hi;
            unpack2(c2[i][j], lo, hi);
            g_V[rowb + 2 * j]     -= lo;
            g_V[rowb + 2 * j + 1] -= hi;
        }
    }
}

// ---------------- mu = v^T z  (z = V[:,8192]) ----------------
__global__ void k_mu(float* __restrict__ out) {
    int t = blockIdx.x * blockDim.x + threadIdx.x;
    float acc = 0.f;
#pragma unroll 8
    for (int i = 0; i < NTR; i++)
        acc += g_V[(size_t)i * LDV + t] * g_V[(size_t)i * LDV + NTE];
    out[t] = acc;
}

// ---------------- cov = K_ss - v^T v (symmetric, fused epilogue, f32x2) -------
__global__ void __launch_bounds__(256) k_cov(const float* __restrict__ xte,
                                             float* __restrict__ C) {
    int ta = blockIdx.y, tb = blockIdx.x;
    if (tb < ta) return;                          // upper tiles only, mirror on write
    __shared__ float sA[16][132];
    __shared__ float sB[16][132];
    __shared__ float sXa[128][8];
    __shared__ float sXb[128][8];
    int tid = threadIdx.x;
    int tx = tid & 15, ty = tid >> 4;
    for (int idx = tid; idx < 128 * 8; idx += 256) {
        sXa[idx >> 3][idx & 7] = xte[(size_t)(ta * 128 + (idx >> 3)) * 8 + (idx & 7)];
        sXb[idx >> 3][idx & 7] = xte[(size_t)(tb * 128 + (idx >> 3)) * 8 + (idx & 7)];
    }
    ull c2[8][4];
#pragma unroll
    for (int i = 0; i < 8; i++)
#pragma unroll
        for (int j = 0; j < 4; j++) c2[i][j] = 0ull;

    for (int kk = 0; kk < NTR; kk += 16) {
#pragma unroll
        for (int l = 0; l < 2; l++) {
            int idx = tid + l * 256;
            int p = idx >> 5, cc = (idx & 31) * 4;
            *(float4*)&sA[p][cc] = *(const float4*)&g_V[(size_t)(kk + p) * LDV + ta * 128 + cc];
            *(float4*)&sB[p][cc] = *(const float4*)&g_V[(size_t)(kk + p) * LDV + tb * 128 + cc];
        }
        __syncthreads();
#pragma unroll
        for (int p = 0; p < 16; p++) {
            float a[8];
            *(float4*)&a[0] = *(const float4*)&sA[p][ty * 8];
            *(float4*)&a[4] = *(const float4*)&sA[p][ty * 8 + 4];
            ull b2[4];
#pragma unroll
            for (int j = 0; j < 4; j++)
                b2[j] = *(const ull*)&sB[p][tx * 8 + 2 * j];
#pragma unroll
            for (int i = 0; i < 8; i++) {
                ull a2 = pack2(a[i], a[i]);
#pragma unroll
                for (int j = 0; j < 4; j++) fma2(c2[i][j], a2, b2[j]);
            }
        }
        __syncthreads();
    }
    float p0 = g_par[0], var = g_par[1];
#pragma unroll
    for (int i = 0; i < 8; i++) {
        int ga = ta * 128 + ty * 8 + i;
#pragma unroll
        for (int j = 0; j < 4; j++) {
            float clo, chi;
            unpack2(c2[i][j], clo, chi);
#pragma unroll
            for (int h = 0; h < 2; h++) {
                int gb = tb * 128 + tx * 8 + 2 * j + h;
                float cv = h ? chi : clo;
                float d2 = 0.f;
#pragma unroll
                for (int d = 0; d < 8; d++) {
                    float df = sXa[ty * 8 + i][d] - sXb[tx * 8 + 2 * j + h][d];
                    d2 += df * df;
                }
                float val = var * expf(-p0 * d2) - cv;
                if (ga == gb) val += 1e-6f;
                C[(size_t)ga * NTE + gb] = val;
                C[(size_t)gb * NTE + ga] = val;
            }
        }
    }
}

// ---------------- driver ----------------
extern "C" void kernel_launch(void* const* d_in, const int* in_sizes, int n_in,
                              void* d_out, int out_size) {
    (void)in_sizes; (void)n_in; (void)out_size;
    const float* x_train = (const float*)d_in[0];
    const float* y_train = (const float*)d_in[1];
    const float* w_train = (const float*)d_in[2];
    const float* x_test  = (const float*)d_in[3];
    const float* rls     = (const float*)d_in[4];
    const float* rvar    = (const float*)d_in[5];
    const float* rnv     = (const float*)d_in[6];
    float* out = (float*)d_out;          // [ mu (8192) | cov (8192*8192) ]

    k_params<<<1, 32>>>(rls, rvar, rnv);

    dim3 b16(16, 16);
    k_buildK <<<dim3(NTR / 16, NTR / 16), b16>>>(x_train, w_train);
    k_buildKs<<<dim3(NTE / 16, NTR / 16), b16>>>(x_train, x_test, w_train);
    k_initz  <<<NTR, 128>>>(y_train);

    // blocked Cholesky (in place in g_K)
    for (int k0 = 0; k0 < NTR; k0 += NB) {
        k_potrf<<<1, 64>>>(k0);
        int rows = NTR - k0 - NB;
        if (rows > 0) {
            k_panel<<<(rows + 63) / 64, 64>>>(k0);
            int nt = rows / 64;
            k_syrk<<<dim3(nt, nt), 256>>>(k0);
        }
    }

    // v = L^{-1} [wKs | y | 0]  (right-looking blocked forward substitution)
    for (int k0 = 0; k0 < NTR; k0 += NB) {
        k_diagV<<<LDV / 128, 128>>>(k0);
        int rows = NTR - k0 - NB;
        if (rows > 0)
            k_trsm_update<<<dim3(LDV / 128, rows / 64), 256>>>(k0);
    }

    // mu = v^T z
    k_mu<<<NTE / 128, 128>>>(out);

    // cov = K_ss - v^T v
    k_cov<<<dim3(NTE / 128, NTE / 128), 256>>>(x_test, out + NTE);
}